// round 1
// baseline (speedup 1.0000x reference)
#include <cuda_runtime.h>
#include <math.h>
#include <stdint.h>

#define BB 2
#define NN 100000
#define EE 400000
#define NODE_DIM 32
#define DD 64
#define H0 128
#define H1 64
#define TILE_E 32

// -------- device scratch (no allocations allowed) --------
__device__ float g_hnodes[(size_t)BB * NN * DD];   // 51.2 MB
__device__ float g_sum[BB * DD];
__device__ int   g_cnt[BB];
__device__ int   g_mask_mode;                      // 0=u8, 1=i32, 2=f32

// -------- mask access --------
__device__ __forceinline__ bool mask_at(const void* m, long long i, int mode) {
    if (mode == 1) return ((const int*)m)[i] != 0;
    if (mode == 2) return ((const float*)m)[i] != 0.0f;
    return ((const unsigned char*)m)[i] != 0;
}

// -------- init: zero accumulators + detect mask dtype --------
__global__ void k_init(const unsigned int* mask_words) {
    int t = threadIdx.x;
    if (t < BB * DD) g_sum[t] = 0.0f;
    if (t < BB) g_cnt[t] = 0;
    __shared__ int s_notint, s_notfl;
    if (t == 0) { s_notint = 0; s_notfl = 0; }
    __syncthreads();
    int ni = 0, nf = 0;
    for (int i = t; i < 1024; i += blockDim.x) {
        unsigned w = mask_words[i];            // mask buffer >= 800000 bytes, safe
        if (w > 1u) ni = 1;
        if (w != 0u && w != 0x3F800000u) nf = 1;
    }
    if (ni) atomicOr(&s_notint, 1);
    if (nf) atomicOr(&s_notfl, 1);
    __syncthreads();
    if (t == 0) g_mask_mode = (!s_notint) ? 1 : ((!s_notfl) ? 2 : 0);
}

// -------- node MLP: h_nodes = tanh(nf @ Wn + bn) --------
__global__ void k_nodes(const float* __restrict__ nf,
                        const float* __restrict__ Wn,
                        const float* __restrict__ bn) {
    __shared__ float2 ws[NODE_DIM][32];   // (Wn[k][j], Wn[k][j+32])
    __shared__ float2 bs[32];
    int tid = threadIdx.x, lane = tid & 31, w = tid >> 5;
    for (int i = tid; i < NODE_DIM * 32; i += blockDim.x) {
        int k = i >> 5, j = i & 31;
        ws[k][j] = make_float2(Wn[k * DD + j], Wn[k * DD + j + 32]);
    }
    if (tid < 32) bs[tid] = make_float2(bn[tid], bn[tid + 32]);
    __syncthreads();

    const int nrows = BB * NN;
    const int warps = (blockDim.x >> 5) * gridDim.x;
    for (int row = blockIdx.x * (blockDim.x >> 5) + w; row < nrows; row += warps) {
        float x = nf[(size_t)row * NODE_DIM + lane];
        float2 acc = bs[lane];
#pragma unroll
        for (int k = 0; k < NODE_DIM; k++) {
            float v = __shfl_sync(0xffffffffu, x, k);
            float2 wv = ws[k][lane];
            acc.x = fmaf(v, wv.x, acc.x);
            acc.y = fmaf(v, wv.y, acc.y);
        }
        float* o = g_hnodes + (size_t)row * DD;
        o[lane]      = tanhf(acc.x);
        o[lane + 32] = tanhf(acc.y);
    }
}

// -------- count masked edges per batch --------
__global__ void k_count(const void* __restrict__ mask) {
    int mode = g_mask_mode;
    int l0 = 0, l1 = 0;
    for (long long i = (long long)blockIdx.x * blockDim.x + threadIdx.x;
         i < (long long)BB * EE;
         i += (long long)gridDim.x * blockDim.x) {
        if (mask_at(mask, i, mode)) { if (i < EE) l0++; else l1++; }
    }
#pragma unroll
    for (int o = 16; o; o >>= 1) {
        l0 += __shfl_xor_sync(0xffffffffu, l0, o);
        l1 += __shfl_xor_sync(0xffffffffu, l1, o);
    }
    __shared__ int c[2];
    if (threadIdx.x == 0) { c[0] = 0; c[1] = 0; }
    __syncthreads();
    if ((threadIdx.x & 31) == 0) { atomicAdd(&c[0], l0); atomicAdd(&c[1], l1); }
    __syncthreads();
    if (threadIdx.x == 0) { atomicAdd(&g_cnt[0], c[0]); atomicAdd(&g_cnt[1], c[1]); }
}

// -------- edge kernel: gather + 2 fused matvecs + tanh + mask + mean partials --------
// dynamic smem layout (bytes):
//   [0, 32768)          float2 s_w[64][64]   (wsum, wdiff)[k][d]
//   [32768, 49664)      float2 s_h[64][33]   (hs, hd)[k][e]  (pad 33)
//   [49664, 49920)      float  s_be[64]
//   [49920, 50432)      float  s_sum[128]
//   [50432, 50688)      int    s_ei[64]
//   [50688, 50692)      unsigned s_mask
#define EDGE_SMEM 50816

__global__ void __launch_bounds__(128, 4) k_edges(
    const float* __restrict__ We, const float* __restrict__ be,
    const int* __restrict__ eidx, const void* __restrict__ mask,
    float* __restrict__ out_policy)
{
    extern __shared__ unsigned char dsm[];
    float2*   s_w    = (float2*)dsm;
    float2*   s_h    = (float2*)(dsm + 32768);
    float*    s_be   = (float*)(dsm + 49664);
    float*    s_sum  = (float*)(dsm + 49920);
    int*      s_ei   = (int*)(dsm + 50432);
    unsigned* s_mptr = (unsigned*)(dsm + 50688);

    const int tid = threadIdx.x;
    const int lane = tid & 31, w = tid >> 5;
    const int mode = g_mask_mode;

    // precompute (Wa+Wb, Wa-Wb) into smem once per (persistent) block
    for (int i = tid; i < 64 * 64; i += 128) {
        int k = i >> 6, d = i & 63;
        float a = We[k * 64 + d];
        float b = We[(64 + k) * 64 + d];
        s_w[i] = make_float2(a + b, a - b);
    }
    if (tid < 64) s_be[tid] = be[tid];
    if (tid < BB * DD) s_sum[tid] = 0.0f;
    __syncthreads();

    const int tiles_per_b = EE / TILE_E;     // 12500
    const int ntiles = BB * tiles_per_b;

    for (int tile = blockIdx.x; tile < ntiles; tile += gridDim.x) {
        const int b = tile / tiles_per_b;
        const long long e0 = (long long)b * EE + (long long)(tile - b * tiles_per_b) * TILE_E;

        if (tid < TILE_E * 2) s_ei[tid] = eidx[e0 * 2 + tid];
        if (w == 2) {
            bool m = mask_at(mask, e0 + lane, mode);
            unsigned bal = __ballot_sync(0xffffffffu, m);
            if (lane == 0) *s_mptr = bal;
        }
        __syncthreads();

        // gather h1/h2 rows, write (hs,hd) transposed [k][e]
        {
            int e = tid >> 2, r = tid & 3;
            const float4* h1p = (const float4*)(g_hnodes + ((size_t)b * NN + s_ei[2 * e]) * DD);
            const float4* h2p = (const float4*)(g_hnodes + ((size_t)b * NN + s_ei[2 * e + 1]) * DD);
#pragma unroll
            for (int m4 = 0; m4 < 4; m4++) {
                int q = r + 4 * m4;
                float4 a = h1p[q], c = h2p[q];
                int k = q * 4;
                s_h[(k + 0) * 33 + e] = make_float2(a.x + c.x, a.x - c.x);
                s_h[(k + 1) * 33 + e] = make_float2(a.y + c.y, a.y - c.y);
                s_h[(k + 2) * 33 + e] = make_float2(a.z + c.z, a.z - c.z);
                s_h[(k + 3) * 33 + e] = make_float2(a.w + c.w, a.w - c.w);
            }
        }
        __syncthreads();

        // compute: warp w owns d in [16w, 16w+16), lane = edge
        unsigned long long acc[16];
#pragma unroll
        for (int j = 0; j < 16; j++) acc[j] = 0ull;
        const int d0 = w * 16;
#pragma unroll 2
        for (int k = 0; k < 64; k++) {
            unsigned long long h = *(const unsigned long long*)&s_h[k * 33 + lane];
            const ulonglong2* wp = (const ulonglong2*)&s_w[k * 64 + d0];
#pragma unroll
            for (int j2 = 0; j2 < 8; j2++) {
                ulonglong2 ww = wp[j2];
                asm("fma.rn.f32x2 %0, %1, %2, %0;" : "+l"(acc[2 * j2])     : "l"(h), "l"(ww.x));
                asm("fma.rn.f32x2 %0, %1, %2, %0;" : "+l"(acc[2 * j2 + 1]) : "l"(h), "l"(ww.y));
            }
        }

        // epilogue: s=(p+q)/2+be, t=(p-q)/2+be, h = 0.5*(tanh(s)+tanh(t)) * mask
        const bool msk = (*s_mptr >> lane) & 1u;
        float hv[16];
#pragma unroll
        for (int j = 0; j < 16; j++) {
            float p = __uint_as_float((unsigned)(acc[j] & 0xffffffffu));
            float q = __uint_as_float((unsigned)(acc[j] >> 32));
            float bias = s_be[d0 + j];
            float s = fmaf(0.5f, p + q, bias);
            float t = fmaf(0.5f, p - q, bias);
            float v = 0.5f * (tanhf(s) + tanhf(t));
            hv[j] = msk ? v : 0.0f;
        }

        // coalesced-ish write (float4 x4 per lane)
        float4* outp = (float4*)(out_policy + (size_t)(e0 + lane) * DD + d0);
        outp[0] = make_float4(hv[0],  hv[1],  hv[2],  hv[3]);
        outp[1] = make_float4(hv[4],  hv[5],  hv[6],  hv[7]);
        outp[2] = make_float4(hv[8],  hv[9],  hv[10], hv[11]);
        outp[3] = make_float4(hv[12], hv[13], hv[14], hv[15]);

        // mean partials: reduce over 32 edges (lanes) per d
#pragma unroll
        for (int j = 0; j < 16; j++) {
            float v = hv[j];
            v += __shfl_xor_sync(0xffffffffu, v, 16);
            v += __shfl_xor_sync(0xffffffffu, v, 8);
            v += __shfl_xor_sync(0xffffffffu, v, 4);
            v += __shfl_xor_sync(0xffffffffu, v, 2);
            v += __shfl_xor_sync(0xffffffffu, v, 1);
            if (lane == 0) s_sum[b * DD + d0 + j] += v;
        }
        __syncthreads();   // protect s_h/s_ei/s_mask for next tile
    }

    if (tid < BB * DD) atomicAdd(&g_sum[tid], s_sum[tid]);
}

// -------- finalize: h_num MLP, mean, concat into state_value --------
__global__ void k_final(const float* __restrict__ numerical,
                        const float* __restrict__ stage,
                        const float* __restrict__ W1, const float* __restrict__ b1,
                        const float* __restrict__ W2, const float* __restrict__ b2,
                        float* __restrict__ out_value)
{
    __shared__ float t1[BB * H0];
    int t = threadIdx.x;
    if (t < BB * H0) {
        int b = t / H0, j = t % H0;
        float acc = b1[j];
#pragma unroll
        for (int k = 0; k < NODE_DIM; k++) acc = fmaf(numerical[b * NODE_DIM + k], W1[k * H0 + j], acc);
        t1[t] = tanhf(acc);
    }
    __syncthreads();
    if (t < BB * H1) {
        int b = t / H1, j = t % H1;
        float acc = b2[j];
#pragma unroll 8
        for (int k = 0; k < H0; k++) acc = fmaf(t1[b * H0 + k], W2[k * H1 + j], acc);
        out_value[b * 130 + j] = tanhf(acc);
        out_value[b * 130 + 64 + j] = g_sum[b * DD + j] / (float)g_cnt[b];
    }
    if (t < BB * 2) {
        int b = t >> 1, s2 = t & 1;
        out_value[b * 130 + 128 + s2] = stage[b * 2 + s2];
    }
}

// -------- launch --------
extern "C" void kernel_launch(void* const* d_in, const int* in_sizes, int n_in,
                              void* d_out, int out_size) {
    (void)in_sizes; (void)n_in; (void)out_size;
    const float* numerical    = (const float*)d_in[0];
    const float* node_feature = (const float*)d_in[1];
    const int*   edge_index   = (const int*)d_in[2];
    const void*  edge_mask    = d_in[3];
    const float* stage        = (const float*)d_in[4];
    const float* W1 = (const float*)d_in[5];
    const float* b1 = (const float*)d_in[6];
    const float* W2 = (const float*)d_in[7];
    const float* b2 = (const float*)d_in[8];
    const float* Wn = (const float*)d_in[9];
    const float* bn = (const float*)d_in[10];
    const float* We = (const float*)d_in[11];
    const float* be = (const float*)d_in[12];

    float* out        = (float*)d_out;
    float* out_policy = out;
    float* out_value  = out + (size_t)BB * EE * DD;

    cudaFuncSetAttribute(k_edges, cudaFuncAttributeMaxDynamicSharedMemorySize, EDGE_SMEM);

    k_init <<<1, 256>>>((const unsigned int*)edge_mask);
    k_nodes<<<2960, 256>>>(node_feature, Wn, bn);
    k_count<<<128, 256>>>(edge_mask);
    k_edges<<<592, 128, EDGE_SMEM>>>(We, be, edge_index, edge_mask, out_policy);
    k_final<<<1, 256>>>(numerical, stage, W1, b1, W2, b2, out_value);
}